// round 9
// baseline (speedup 1.0000x reference)
#include <cuda_runtime.h>
#include <cuda_bf16.h>
#include <math.h>
#include <stdint.h>

// Problem constants
#define B_   4
#define S_   1024
#define T_   4096
#define H_   32
#define D_   80
#define HID_ 2560
#define QKV_N 7680
#define HALF_ 16
#define SCALE_ 0.11180339887498948f

// ---------------------------------------------------------------------------
// Scratch (device globals)
// ---------------------------------------------------------------------------
__device__ float g_qkv [(size_t)T_ * QKV_N];
__device__ float g_attn[(size_t)T_ * HID_];
__device__ float g_hidT[(size_t)T_ * HID_];
__device__ float g_wqkvT[(size_t)QKV_N * HID_];
__device__ float g_wdT [(size_t)HID_ * HID_];

// ---------------------------------------------------------------------------
// Helpers
// ---------------------------------------------------------------------------
__device__ __forceinline__ float tf32r(float x) {
    uint32_t r;
    asm("cvt.rna.tf32.f32 %0, %1;" : "=r"(r) : "f"(x));
    return __uint_as_float(r);
}

#define CP_ASYNC16(dst, src) \
    asm volatile("cp.async.cg.shared.global [%0], [%1], 16;" :: "r"(dst), "l"(src) : "memory")
#define CP_COMMIT() asm volatile("cp.async.commit_group;" ::: "memory")
#define CP_WAIT0()  asm volatile("cp.async.wait_group 0;" ::: "memory")
#define CP_WAIT1()  asm volatile("cp.async.wait_group 1;" ::: "memory")

#define MMA_TF32(d, a, b) \
    asm volatile("mma.sync.aligned.m16n8k8.row.col.f32.tf32.tf32.f32 " \
        "{%0,%1,%2,%3}, {%4,%5,%6,%7}, {%8,%9}, {%0,%1,%2,%3};" \
        : "+f"((d)[0]), "+f"((d)[1]), "+f"((d)[2]), "+f"((d)[3]) \
        : "r"((a)[0]), "r"((a)[1]), "r"((a)[2]), "r"((a)[3]), \
          "r"((b)[0]), "r"((b)[1]))

__device__ __forceinline__ uint32_t smem_u32(const void* p) {
    uint32_t a;
    asm("{ .reg .u64 t; cvta.to.shared.u64 t, %1; cvt.u32.u64 %0, t; }"
        : "=r"(a) : "l"(p));
    return a;
}

// ---------------------------------------------------------------------------
// tf32 mma.sync GEMM: C = A @ W^T + bias
// CTA 128x128, BK=32, 8 warps (64x32 each), 2 CTAs/SM.
// THREE-stage cp.async ring, ONE __syncthreads per chunk:
//   wait(group i) -> barrier -> prefetch stage (i+2)%3 -> compute stage i%3
// PITCH=36 floats (144B rows, conflict-free frag reads).
// ---------------------------------------------------------------------------
#define GM 128
#define GN 128
#define GKC 32
#define PITCH 36
#define NST 3
#define STG (128 * PITCH)                 // 4608 floats per stage per operand
#define GEMM_SMEM (NST * 2 * STG * 4)     // 110592 bytes

__global__ __launch_bounds__(256, 2) void mma_gemm(
    const float* __restrict__ A, const float* __restrict__ W,
    const float* __restrict__ bias, float* __restrict__ C,
    int M, int N, int K, int roundOut)
{
    extern __shared__ float smf[];
    float* Asm = smf;                     // [NST][STG]
    float* Bsm = smf + NST * STG;         // [NST][STG]

    const int tid  = threadIdx.x;
    const int wid  = tid >> 5;
    const int lane = tid & 31;
    const int gid  = lane >> 2;
    const int tig  = lane & 3;
    const int wm   = wid >> 2;
    const int wn   = wid & 3;
    const int m0 = blockIdx.y * GM;
    const int n0 = blockIdx.x * GN;
    const int nk = K / GKC;

    const uint32_t sa = smem_u32(Asm);
    const uint32_t sb = smem_u32(Bsm);

    // cp.async mapping: 128 rows x 8 float4-chunks per operand -> 4/thread.
    const int rowL = tid >> 3;            // 0..31
    const int kcL  = tid & 7;             // 0..7
    const float* srcA0 = A + (size_t)(m0 + rowL) * K + kcL * 4;
    const float* srcB0 = W + (size_t)(n0 + rowL) * K + kcL * 4;
    const uint32_t d0 = (uint32_t)(rowL * 144 + kcL * 16);
    const size_t rstep = (size_t)32 * K;

    float acc[4][4][4];
#pragma unroll
    for (int mt = 0; mt < 4; mt++)
#pragma unroll
        for (int nt = 0; nt < 4; nt++)
#pragma unroll
            for (int r = 0; r < 4; r++) acc[mt][nt][r] = 0.0f;

    // Prologue: stages 0 and 1, each its own commit group.
#pragma unroll
    for (int st = 0; st < 2; st++) {
        const uint32_t ab = sa + st * (STG * 4);
        const uint32_t bb = sb + st * (STG * 4);
        const int kt = st * GKC;
#pragma unroll
        for (int u = 0; u < 4; u++) {
            CP_ASYNC16(ab + d0 + u * 4608, srcA0 + kt + u * rstep);
            CP_ASYNC16(bb + d0 + u * 4608, srcB0 + kt + u * rstep);
        }
        CP_COMMIT();
    }

    int s = 0;       // compute stage
    int ws = 2;      // write (prefetch) stage = (s+2)%3
    for (int i = 0; i < nk; i++) {
        if (i == nk - 1) CP_WAIT0(); else CP_WAIT1();
        __syncthreads();   // covers both: stage i ready for all, and all warps
                           // done reading stage (i-1)%3 == ws before we overwrite

        if (i + 2 < nk) {
            const int kt = (i + 2) * GKC;
            const uint32_t ab = sa + ws * (STG * 4);
            const uint32_t bb = sb + ws * (STG * 4);
#pragma unroll
            for (int u = 0; u < 4; u++) {
                CP_ASYNC16(ab + d0 + u * 4608, srcA0 + kt + u * rstep);
                CP_ASYNC16(bb + d0 + u * 4608, srcB0 + kt + u * rstep);
            }
            CP_COMMIT();
        }

        const float* as = Asm + s * STG;
        const float* bs = Bsm + s * STG;
#pragma unroll
        for (int ks = 0; ks < 4; ks++) {
            const int k0 = ks * 8;
            uint32_t af[4][4], bf[4][2];
#pragma unroll
            for (int mt = 0; mt < 4; mt++) {
                int r = wm * 64 + mt * 16 + gid;
                af[mt][0] = __float_as_uint(as[r * PITCH + k0 + tig]);
                af[mt][1] = __float_as_uint(as[(r + 8) * PITCH + k0 + tig]);
                af[mt][2] = __float_as_uint(as[r * PITCH + k0 + tig + 4]);
                af[mt][3] = __float_as_uint(as[(r + 8) * PITCH + k0 + tig + 4]);
            }
#pragma unroll
            for (int nt = 0; nt < 4; nt++) {
                int c = wn * 32 + nt * 8 + gid;
                bf[nt][0] = __float_as_uint(bs[c * PITCH + k0 + tig]);
                bf[nt][1] = __float_as_uint(bs[c * PITCH + k0 + tig + 4]);
            }
#pragma unroll
            for (int mt = 0; mt < 4; mt++)
#pragma unroll
                for (int nt = 0; nt < 4; nt++)
                    MMA_TF32(acc[mt][nt], af[mt], bf[nt]);
        }

        s  = (s  == NST - 1) ? 0 : s + 1;
        ws = (ws == NST - 1) ? 0 : ws + 1;
    }

#pragma unroll
    for (int mt = 0; mt < 4; mt++) {
        int r = m0 + wm * 64 + mt * 16 + gid;
#pragma unroll
        for (int nt = 0; nt < 4; nt++) {
            int c = n0 + wn * 32 + nt * 8 + tig * 2;
            float b0 = bias[c], b1 = bias[c + 1];
            float o0 = acc[mt][nt][0] + b0, o1 = acc[mt][nt][1] + b1;
            float o2 = acc[mt][nt][2] + b0, o3 = acc[mt][nt][3] + b1;
            if (roundOut) {
                o0 = tf32r(o0); o1 = tf32r(o1); o2 = tf32r(o2); o3 = tf32r(o3);
            }
            *(float2*)(C + (size_t)r * N + c)       = make_float2(o0, o1);
            *(float2*)(C + (size_t)(r + 8) * N + c) = make_float2(o2, o3);
        }
    }
}

// ---------------------------------------------------------------------------
// tf32 round (RNA) elementwise convert
// ---------------------------------------------------------------------------
__global__ __launch_bounds__(256) void cvt_tf32_kernel(
    const float4* __restrict__ in, float4* __restrict__ out, int n4)
{
    int i = blockIdx.x * 256 + threadIdx.x;
    if (i >= n4) return;
    float4 v = in[i];
    v.x = tf32r(v.x); v.y = tf32r(v.y); v.z = tf32r(v.z); v.w = tf32r(v.w);
    out[i] = v;
}

// ---------------------------------------------------------------------------
// Partial rotary (in place on q,k of qkv), outputs re-rounded to tf32.
// ---------------------------------------------------------------------------
__global__ __launch_bounds__(256) void rope_kernel(
    float* __restrict__ qkv, const float* __restrict__ cosp,
    const float* __restrict__ sinp)
{
    int idx = blockIdx.x * blockDim.x + threadIdx.x;
    int i = idx & (HALF_ - 1);
    int h = (idx >> 4) & (H_ - 1);
    int t = (idx >> 9) & (T_ - 1);
    int which = idx >> 21;
    float* base = qkv + (size_t)t * QKV_N + which * HID_ + h * D_;
    float c = cosp[t * HALF_ + i];
    float s = sinp[t * HALF_ + i];
    float x1 = base[i];
    float x2 = base[i + HALF_];
    base[i]         = tf32r(x1 * c - x2 * s);
    base[i + HALF_] = tf32r(x2 * c + x1 * s);
}

// ---------------------------------------------------------------------------
// Causal flash attention via mma.sync tf32 (Round-7 proven).
// ---------------------------------------------------------------------------
#define AQ 64
#define AKV 64
#define PQA 84
#define PVA 88
#define PPS 76
#define ATTN_SMEM_FLOATS (AQ*PQA + AKV*PQA + AKV*PVA + AQ*PPS)
#define ATTN_SMEM_BYTES  (ATTN_SMEM_FLOATS * 4)

__global__ __launch_bounds__(128) void attn_kernel(
    const float* __restrict__ qkv, float* __restrict__ outp)
{
    extern __shared__ float sm[];
    float* Qs = sm;
    float* Ks = Qs + AQ * PQA;
    float* Vs = Ks + AKV * PQA;
    float* Ps = Vs + AKV * PVA;

    const int bh = blockIdx.y;
    const int b  = bh >> 5;
    const int h  = bh & 31;
    const int qt = blockIdx.x;
    const int q0 = qt * AQ;
    const int tid = threadIdx.x;
    const int lane = tid & 31;
    const int w = tid >> 5;
    const int gid = lane >> 2;
    const int tig = lane & 3;
    const int rq = w * 16;

    const float* Qg = qkv + (size_t)(b * S_) * QKV_N + h * D_;
    const float* Kg = Qg + HID_;
    const float* Vg = Qg + 2 * HID_;

    for (int u = tid; u < AQ * 20; u += 128) {
        int r = u / 20, c4 = u % 20;
        *(float4*)&Qs[r * PQA + c4 * 4] =
            *(const float4*)(Qg + (size_t)(q0 + r) * QKV_N + c4 * 4);
    }

    float m0v = -1e30f, m1v = -1e30f, l0 = 0.0f, l1 = 0.0f;
    float oacc[10][4];
#pragma unroll
    for (int nt = 0; nt < 10; nt++)
#pragma unroll
        for (int r = 0; r < 4; r++) oacc[nt][r] = 0.0f;

    for (int jt = 0; jt <= qt; jt++) {
        for (int u = tid; u < AKV * 20; u += 128) {
            int r = u / 20, c4 = u % 20;
            *(float4*)&Ks[r * PQA + c4 * 4] =
                *(const float4*)(Kg + (size_t)(jt * AKV + r) * QKV_N + c4 * 4);
            *(float4*)&Vs[r * PVA + c4 * 4] =
                *(const float4*)(Vg + (size_t)(jt * AKV + r) * QKV_N + c4 * 4);
        }
        __syncthreads();

        float sacc[8][4];
#pragma unroll
        for (int nt = 0; nt < 8; nt++)
#pragma unroll
            for (int r = 0; r < 4; r++) sacc[nt][r] = 0.0f;

#pragma unroll
        for (int kf = 0; kf < 10; kf++) {
            const int k0 = kf * 8;
            uint32_t af[4];
            af[0] = __float_as_uint(Qs[(rq + gid) * PQA + k0 + tig]);
            af[1] = __float_as_uint(Qs[(rq + gid + 8) * PQA + k0 + tig]);
            af[2] = __float_as_uint(Qs[(rq + gid) * PQA + k0 + tig + 4]);
            af[3] = __float_as_uint(Qs[(rq + gid + 8) * PQA + k0 + tig + 4]);
#pragma unroll
            for (int nt = 0; nt < 8; nt++) {
                uint32_t bf[2];
                bf[0] = __float_as_uint(Ks[(nt * 8 + gid) * PQA + k0 + tig]);
                bf[1] = __float_as_uint(Ks[(nt * 8 + gid) * PQA + k0 + tig + 4]);
                MMA_TF32(sacc[nt], af, bf);
            }
        }

        const int r0 = q0 + rq + gid;
        const int r1 = r0 + 8;
#pragma unroll
        for (int nt = 0; nt < 8; nt++) {
            int c0 = jt * AKV + nt * 8 + 2 * tig;
            int c1 = c0 + 1;
            sacc[nt][0] = (c0 > r0) ? -1e30f : sacc[nt][0] * SCALE_;
            sacc[nt][1] = (c1 > r0) ? -1e30f : sacc[nt][1] * SCALE_;
            sacc[nt][2] = (c0 > r1) ? -1e30f : sacc[nt][2] * SCALE_;
            sacc[nt][3] = (c1 > r1) ? -1e30f : sacc[nt][3] * SCALE_;
        }

        float rmax0 = -1e30f, rmax1 = -1e30f;
#pragma unroll
        for (int nt = 0; nt < 8; nt++) {
            rmax0 = fmaxf(rmax0, fmaxf(sacc[nt][0], sacc[nt][1]));
            rmax1 = fmaxf(rmax1, fmaxf(sacc[nt][2], sacc[nt][3]));
        }
#pragma unroll
        for (int o = 1; o <= 2; o <<= 1) {
            rmax0 = fmaxf(rmax0, __shfl_xor_sync(0xffffffffu, rmax0, o));
            rmax1 = fmaxf(rmax1, __shfl_xor_sync(0xffffffffu, rmax1, o));
        }
        float mnew0 = fmaxf(m0v, rmax0), mnew1 = fmaxf(m1v, rmax1);
        float alpha0 = __expf(m0v - mnew0), alpha1 = __expf(m1v - mnew1);

        float rsum0 = 0.0f, rsum1 = 0.0f;
#pragma unroll
        for (int nt = 0; nt < 8; nt++) {
            float p0 = __expf(sacc[nt][0] - mnew0);
            float p1 = __expf(sacc[nt][1] - mnew0);
            float p2 = __expf(sacc[nt][2] - mnew1);
            float p3 = __expf(sacc[nt][3] - mnew1);
            rsum0 += p0 + p1;
            rsum1 += p2 + p3;
            *(float2*)&Ps[(rq + gid) * PPS + nt * 8 + 2 * tig] =
                make_float2(tf32r(p0), tf32r(p1));
            *(float2*)&Ps[(rq + gid + 8) * PPS + nt * 8 + 2 * tig] =
                make_float2(tf32r(p2), tf32r(p3));
        }
#pragma unroll
        for (int o = 1; o <= 2; o <<= 1) {
            rsum0 += __shfl_xor_sync(0xffffffffu, rsum0, o);
            rsum1 += __shfl_xor_sync(0xffffffffu, rsum1, o);
        }
        l0 = l0 * alpha0 + rsum0;  m0v = mnew0;
        l1 = l1 * alpha1 + rsum1;  m1v = mnew1;
#pragma unroll
        for (int nt = 0; nt < 10; nt++) {
            oacc[nt][0] *= alpha0; oacc[nt][1] *= alpha0;
            oacc[nt][2] *= alpha1; oacc[nt][3] *= alpha1;
        }
        __syncwarp();

#pragma unroll
        for (int kf = 0; kf < 8; kf++) {
            const int k0 = kf * 8;
            uint32_t af[4];
            af[0] = __float_as_uint(Ps[(rq + gid) * PPS + k0 + tig]);
            af[1] = __float_as_uint(Ps[(rq + gid + 8) * PPS + k0 + tig]);
            af[2] = __float_as_uint(Ps[(rq + gid) * PPS + k0 + tig + 4]);
            af[3] = __float_as_uint(Ps[(rq + gid + 8) * PPS + k0 + tig + 4]);
#pragma unroll
            for (int nt = 0; nt < 10; nt++) {
                uint32_t bf[2];
                bf[0] = __float_as_uint(Vs[(k0 + tig) * PVA + nt * 8 + gid]);
                bf[1] = __float_as_uint(Vs[(k0 + tig + 4) * PVA + nt * 8 + gid]);
                MMA_TF32(oacc[nt], af, bf);
            }
        }
        __syncthreads();
    }

    const float inv0 = 1.0f / l0, inv1 = 1.0f / l1;
    const int gr0 = b * S_ + q0 + rq + gid;
    float* o0p = outp + (size_t)gr0 * HID_ + h * D_;
    float* o1p = o0p + 8 * HID_;
#pragma unroll
    for (int nt = 0; nt < 10; nt++) {
        int c = nt * 8 + 2 * tig;
        *(float2*)(o0p + c) = make_float2(tf32r(oacc[nt][0] * inv0),
                                          tf32r(oacc[nt][1] * inv0));
        *(float2*)(o1p + c) = make_float2(tf32r(oacc[nt][2] * inv1),
                                          tf32r(oacc[nt][3] * inv1));
    }
}

// ---------------------------------------------------------------------------
// kernel_launch
// ---------------------------------------------------------------------------
extern "C" void kernel_launch(void* const* d_in, const int* in_sizes, int n_in,
                              void* d_out, int out_size)
{
    const float* hidden  = (const float*)d_in[0];
    const float* cosp    = (const float*)d_in[1];
    const float* sinp    = (const float*)d_in[2];
    const float* w_qkv   = (const float*)d_in[3];
    const float* b_qkv   = (const float*)d_in[4];
    const float* w_dense = (const float*)d_in[5];
    const float* b_dense = (const float*)d_in[6];
    float* outp = (float*)d_out;

    float *qkv, *attn, *hidT, *wqkvT, *wdT;
    cudaGetSymbolAddress((void**)&qkv,   g_qkv);
    cudaGetSymbolAddress((void**)&attn,  g_attn);
    cudaGetSymbolAddress((void**)&hidT,  g_hidT);
    cudaGetSymbolAddress((void**)&wqkvT, g_wqkvT);
    cudaGetSymbolAddress((void**)&wdT,   g_wdT);

    cudaFuncSetAttribute(mma_gemm,
                         cudaFuncAttributeMaxDynamicSharedMemorySize, GEMM_SMEM);
    cudaFuncSetAttribute(attn_kernel,
                         cudaFuncAttributeMaxDynamicSharedMemorySize, ATTN_SMEM_BYTES);

    // 0) round inputs to tf32 (RNA, unbiased)
    cvt_tf32_kernel<<<(T_ * HID_ / 4 + 255) / 256, 256>>>(
        (const float4*)hidden, (float4*)hidT, T_ * HID_ / 4);
    cvt_tf32_kernel<<<((size_t)QKV_N * HID_ / 4 + 255) / 256, 256>>>(
        (const float4*)w_qkv, (float4*)wqkvT, QKV_N * HID_ / 4);
    cvt_tf32_kernel<<<((size_t)HID_ * HID_ / 4 + 255) / 256, 256>>>(
        (const float4*)w_dense, (float4*)wdT, HID_ * HID_ / 4);

    // 1) QKV GEMM (mma.sync tf32) + bias, tf32-rounded output
    {
        dim3 grid(QKV_N / GN, T_ / GM);   // (60, 32)
        mma_gemm<<<grid, 256, GEMM_SMEM>>>(hidT, wqkvT, b_qkv, qkv,
                                           T_, QKV_N, HID_, 1);
    }

    // 2) partial RoPE (re-rounds rotated dims)
    {
        int total = 2 * T_ * H_ * HALF_;
        rope_kernel<<<total / 256, 256>>>(qkv, cosp, sinp);
    }

    // 3) causal flash attention (mma.sync tf32)
    {
        dim3 grid(S_ / AQ, B_ * H_);      // (16, 128)
        attn_kernel<<<grid, 128, ATTN_SMEM_BYTES>>>(qkv, attn);
    }

    // 4) dense GEMM (mma.sync tf32) + bias -> final output (no rounding)
    {
        dim3 grid(HID_ / GN, T_ / GM);    // (20, 32)
        mma_gemm<<<grid, 256, GEMM_SMEM>>>(attn, wdT, b_dense, outp,
                                           T_, HID_, HID_, 0);
    }
}

// round 10
// speedup vs baseline: 1.9600x; 1.9600x over previous
#include <cuda_runtime.h>
#include <cuda_fp16.h>
#include <math.h>
#include <stdint.h>

// Problem constants
#define B_   4
#define S_   1024
#define T_   4096
#define H_   32
#define D_   80
#define HID_ 2560
#define QKV_N 7680
#define HALF_ 16
#define SCALE_ 0.11180339887498948f

// ---------------------------------------------------------------------------
// Scratch (device globals)
// ---------------------------------------------------------------------------
__device__ __half g_qkv [(size_t)T_ * QKV_N];
__device__ __half g_attn[(size_t)T_ * HID_];
__device__ __half g_hidH[(size_t)T_ * HID_];
__device__ __half g_wqkvH[(size_t)QKV_N * HID_];
__device__ __half g_wdH [(size_t)HID_ * HID_];

// ---------------------------------------------------------------------------
// Helpers
// ---------------------------------------------------------------------------
#define CP_ASYNC16(dst, src) \
    asm volatile("cp.async.cg.shared.global [%0], [%1], 16;" :: "r"(dst), "l"(src) : "memory")
#define CP_COMMIT() asm volatile("cp.async.commit_group;" ::: "memory")
#define CP_WAIT0()  asm volatile("cp.async.wait_group 0;" ::: "memory")
#define CP_WAIT1()  asm volatile("cp.async.wait_group 1;" ::: "memory")

// m16n8k16 fp16 mma, fp32 accumulate. a: 4x b32 (half2), b: 2x b32.
#define MMA_F16(d, a, b) \
    asm volatile("mma.sync.aligned.m16n8k16.row.col.f32.f16.f16.f32 " \
        "{%0,%1,%2,%3}, {%4,%5,%6,%7}, {%8,%9}, {%0,%1,%2,%3};" \
        : "+f"((d)[0]), "+f"((d)[1]), "+f"((d)[2]), "+f"((d)[3]) \
        : "r"((a)[0]), "r"((a)[1]), "r"((a)[2]), "r"((a)[3]), \
          "r"((b)[0]), "r"((b)[1]))

__device__ __forceinline__ uint32_t smem_u32(const void* p) {
    uint32_t a;
    asm("{ .reg .u64 t; cvta.to.shared.u64 t, %1; cvt.u32.u64 %0, t; }"
        : "=r"(a) : "l"(p));
    return a;
}
__device__ __forceinline__ uint32_t packh2(float lo, float hi) {
    __half2 h = __floats2half2_rn(lo, hi);
    return *(uint32_t*)&h;
}

// ---------------------------------------------------------------------------
// fp16 mma.sync GEMM: C = A @ W^T + bias.  A:[M][K] half, W:[N][K] half.
// CTA 128x128, GKC=64 halves, 8 warps (64x32 each), 2 CTAs/SM,
// double-buffered cp.async (R8-proven pipeline), pitch 72 halves (144B).
// outHalf!=0 -> C is __half*, else float*.
// ---------------------------------------------------------------------------
#define GM 128
#define GN 128
#define GKC 64
#define PH 72
#define STGH (128 * PH)                   // halves per stage per operand
#define GEMM_SMEM (2 * 2 * STGH * 2)      // 73728 bytes

__global__ __launch_bounds__(256, 2) void mma_gemm(
    const __half* __restrict__ A, const __half* __restrict__ W,
    const float* __restrict__ bias, void* __restrict__ Cv,
    int M, int N, int K, int outHalf)
{
    extern __shared__ __align__(16) uint32_t sm32[];
    uint32_t* Asm = sm32;                  // [2][STGH/2] uint32
    uint32_t* Bsm = sm32 + STGH;           // (2 stages A = STGH uint32 total)

    const int tid  = threadIdx.x;
    const int wid  = tid >> 5;
    const int lane = tid & 31;
    const int g    = lane >> 2;
    const int t    = lane & 3;
    const int wm   = wid >> 2;
    const int wn   = wid & 3;
    const int m0 = blockIdx.y * GM;
    const int n0 = blockIdx.x * GN;
    const int nk = K / GKC;

    const uint32_t sa = smem_u32(Asm);
    const uint32_t sb = smem_u32(Bsm);

    // cp.async: per operand per stage 128 rows x 8 x16B chunks -> 4/thread.
    const int rowL = tid >> 3;             // 0..31
    const int cL   = tid & 7;              // 0..7
    const __half* srcA0 = A + (size_t)(m0 + rowL) * K + cL * 8;
    const __half* srcB0 = W + (size_t)(n0 + rowL) * K + cL * 8;
    const uint32_t d0 = (uint32_t)(rowL * 144 + cL * 16);
    const size_t rstep = (size_t)32 * K;   // halves, u advances 32 rows

    float acc[4][4][4];
#pragma unroll
    for (int mt = 0; mt < 4; mt++)
#pragma unroll
        for (int nt = 0; nt < 4; nt++)
#pragma unroll
            for (int r = 0; r < 4; r++) acc[mt][nt][r] = 0.0f;

    // Prologue: stage 0, chunk 0
#pragma unroll
    for (int u = 0; u < 4; u++) {
        CP_ASYNC16(sa + d0 + u * 4608, srcA0 + u * rstep);
        CP_ASYNC16(sb + d0 + u * 4608, srcB0 + u * rstep);
    }
    CP_COMMIT();

    for (int i = 0; i < nk; i++) {
        const int s = i & 1;
        if (i + 1 < nk) {
            const int s2 = (i + 1) & 1;
            const int kt = (i + 1) * GKC;
            const uint32_t ab = sa + s2 * (STGH * 2);
            const uint32_t bb = sb + s2 * (STGH * 2);
#pragma unroll
            for (int u = 0; u < 4; u++) {
                CP_ASYNC16(ab + d0 + u * 4608, srcA0 + kt + u * rstep);
                CP_ASYNC16(bb + d0 + u * 4608, srcB0 + kt + u * rstep);
            }
            CP_COMMIT();
            CP_WAIT1();
        } else {
            CP_WAIT0();
        }
        __syncthreads();

        const uint32_t* as = Asm + s * (STGH / 2);
        const uint32_t* bs = Bsm + s * (STGH / 2);
#pragma unroll
        for (int ks = 0; ks < 4; ks++) {       // 4 x k16 steps = 64 K
            uint32_t af[4][4], bf[4][2];
#pragma unroll
            for (int mt = 0; mt < 4; mt++) {
                int r = wm * 64 + mt * 16 + g;
                int base0 = r * 36 + ks * 8 + t;
                int base1 = (r + 8) * 36 + ks * 8 + t;
                af[mt][0] = as[base0];
                af[mt][1] = as[base1];
                af[mt][2] = as[base0 + 4];
                af[mt][3] = as[base1 + 4];
            }
#pragma unroll
            for (int nt = 0; nt < 4; nt++) {
                int c = wn * 32 + nt * 8 + g;
                int base = c * 36 + ks * 8 + t;
                bf[nt][0] = bs[base];
                bf[nt][1] = bs[base + 4];
            }
#pragma unroll
            for (int mt = 0; mt < 4; mt++)
#pragma unroll
                for (int nt = 0; nt < 4; nt++)
                    MMA_F16(acc[mt][nt], af[mt], bf[nt]);
        }
        __syncthreads();
    }

    // Epilogue: bias + store (C-fragment mapping same as k8 version).
#pragma unroll
    for (int mt = 0; mt < 4; mt++) {
        int r = m0 + wm * 64 + mt * 16 + g;
#pragma unroll
        for (int nt = 0; nt < 4; nt++) {
            int c = n0 + wn * 32 + nt * 8 + t * 2;
            float b0 = bias[c], b1 = bias[c + 1];
            float o0 = acc[mt][nt][0] + b0, o1 = acc[mt][nt][1] + b1;
            float o2 = acc[mt][nt][2] + b0, o3 = acc[mt][nt][3] + b1;
            if (outHalf) {
                __half* C = (__half*)Cv;
                *(uint32_t*)(C + (size_t)r * N + c)       = packh2(o0, o1);
                *(uint32_t*)(C + (size_t)(r + 8) * N + c) = packh2(o2, o3);
            } else {
                float* C = (float*)Cv;
                *(float2*)(C + (size_t)r * N + c)       = make_float2(o0, o1);
                *(float2*)(C + (size_t)(r + 8) * N + c) = make_float2(o2, o3);
            }
        }
    }
}

// ---------------------------------------------------------------------------
// fp32 -> fp16 convert (RN)
// ---------------------------------------------------------------------------
__global__ __launch_bounds__(256) void cvt_h_kernel(
    const float4* __restrict__ in, uint2* __restrict__ out, int n4)
{
    int i = blockIdx.x * 256 + threadIdx.x;
    if (i >= n4) return;
    float4 v = in[i];
    uint2 o;
    o.x = packh2(v.x, v.y);
    o.y = packh2(v.z, v.w);
    out[i] = o;
}

// ---------------------------------------------------------------------------
// Partial rotary on fp16 qkv (in place), fp32 math.
// ---------------------------------------------------------------------------
__global__ __launch_bounds__(256) void rope_kernel(
    __half* __restrict__ qkv, const float* __restrict__ cosp,
    const float* __restrict__ sinp)
{
    int idx = blockIdx.x * blockDim.x + threadIdx.x;
    int i = idx & (HALF_ - 1);
    int h = (idx >> 4) & (H_ - 1);
    int t = (idx >> 9) & (T_ - 1);
    int which = idx >> 21;
    __half* base = qkv + (size_t)t * QKV_N + which * HID_ + h * D_;
    float c = cosp[t * HALF_ + i];
    float s = sinp[t * HALF_ + i];
    float x1 = __half2float(base[i]);
    float x2 = __half2float(base[i + HALF_]);
    base[i]         = __float2half_rn(x1 * c - x2 * s);
    base[i + HALF_] = __float2half_rn(x2 * c + x1 * s);
}

// ---------------------------------------------------------------------------
// Causal flash attention, fp16 mma.sync m16n8k16.
// 128 threads / 4 warps; warp w owns q-rows 16w..16w+15 of a 64-row tile.
// Pitches (halves): Q/K/V 88, P 72 (conflict-free per derivation).
// ---------------------------------------------------------------------------
#define AQ 64
#define AKV 64
#define PQh 88
#define PPh 72
#define ATTN_SMEM_BYTES ((3 * AQ * PQh + AQ * PPh) * 2)   // 43008

__global__ __launch_bounds__(128) void attn_kernel(
    const __half* __restrict__ qkv, __half* __restrict__ outp)
{
    extern __shared__ __align__(16) __half smh[];
    __half* Qs = smh;                    // [64][88]
    __half* Ks = Qs + AQ * PQh;
    __half* Vs = Ks + AKV * PQh;
    __half* Ps = Vs + AKV * PQh;         // [64][72]
    const uint32_t* Qs32 = (const uint32_t*)Qs;
    const uint32_t* Ks32 = (const uint32_t*)Ks;
    const uint32_t* Ps32 = (const uint32_t*)Ps;
    uint32_t* Psw32 = (uint32_t*)Ps;

    const int bh = blockIdx.y;
    const int b  = bh >> 5;
    const int h  = bh & 31;
    const int qt = blockIdx.x;
    const int q0 = qt * AQ;
    const int tid = threadIdx.x;
    const int lane = tid & 31;
    const int w = tid >> 5;
    const int g = lane >> 2;
    const int t = lane & 3;
    const int rq = w * 16;

    const __half* Qg = qkv + (size_t)(b * S_) * QKV_N + h * D_;
    const __half* Kg = Qg + HID_;
    const __half* Vg = Qg + 2 * HID_;

    // Load Q tile: 64 rows x 10 chunks of 8 halves
    {
        uint4* Q4 = (uint4*)Qs;
        for (int u = tid; u < AQ * 10; u += 128) {
            int r = u / 10, c8 = u % 10;
            Q4[r * 11 + c8] = *(const uint4*)(Qg + (size_t)(q0 + r) * QKV_N + c8 * 8);
        }
    }

    float m0v = -1e30f, m1v = -1e30f, l0 = 0.0f, l1 = 0.0f;
    float oacc[10][4];
#pragma unroll
    for (int nt = 0; nt < 10; nt++)
#pragma unroll
        for (int r = 0; r < 4; r++) oacc[nt][r] = 0.0f;

    for (int jt = 0; jt <= qt; jt++) {
        {
            uint4* K4 = (uint4*)Ks;
            uint4* V4 = (uint4*)Vs;
            for (int u = tid; u < AKV * 10; u += 128) {
                int r = u / 10, c8 = u % 10;
                K4[r * 11 + c8] = *(const uint4*)(Kg + (size_t)(jt * AKV + r) * QKV_N + c8 * 8);
                V4[r * 11 + c8] = *(const uint4*)(Vg + (size_t)(jt * AKV + r) * QKV_N + c8 * 8);
            }
        }
        __syncthreads();

        // ---- S = Q K^T ----
        float sacc[8][4];
#pragma unroll
        for (int nt = 0; nt < 8; nt++)
#pragma unroll
            for (int r = 0; r < 4; r++) sacc[nt][r] = 0.0f;

#pragma unroll
        for (int kf = 0; kf < 5; kf++) {     // 5 x k16 = 80 dims
            uint32_t af[4];
            int ba0 = (rq + g) * 44 + kf * 8 + t;
            int ba1 = (rq + g + 8) * 44 + kf * 8 + t;
            af[0] = Qs32[ba0];
            af[1] = Qs32[ba1];
            af[2] = Qs32[ba0 + 4];
            af[3] = Qs32[ba1 + 4];
#pragma unroll
            for (int nt = 0; nt < 8; nt++) {
                uint32_t bf[2];
                int bb = (nt * 8 + g) * 44 + kf * 8 + t;
                bf[0] = Ks32[bb];
                bf[1] = Ks32[bb + 4];
                MMA_F16(sacc[nt], af, bf);
            }
        }

        // ---- scale + causal mask ----
        const int r0 = q0 + rq + g;
        const int r1 = r0 + 8;
#pragma unroll
        for (int nt = 0; nt < 8; nt++) {
            int c0 = jt * AKV + nt * 8 + 2 * t;
            int c1 = c0 + 1;
            sacc[nt][0] = (c0 > r0) ? -1e30f : sacc[nt][0] * SCALE_;
            sacc[nt][1] = (c1 > r0) ? -1e30f : sacc[nt][1] * SCALE_;
            sacc[nt][2] = (c0 > r1) ? -1e30f : sacc[nt][2] * SCALE_;
            sacc[nt][3] = (c1 > r1) ? -1e30f : sacc[nt][3] * SCALE_;
        }

        // ---- online softmax ----
        float rmax0 = -1e30f, rmax1 = -1e30f;
#pragma unroll
        for (int nt = 0; nt < 8; nt++) {
            rmax0 = fmaxf(rmax0, fmaxf(sacc[nt][0], sacc[nt][1]));
            rmax1 = fmaxf(rmax1, fmaxf(sacc[nt][2], sacc[nt][3]));
        }
#pragma unroll
        for (int o = 1; o <= 2; o <<= 1) {
            rmax0 = fmaxf(rmax0, __shfl_xor_sync(0xffffffffu, rmax0, o));
            rmax1 = fmaxf(rmax1, __shfl_xor_sync(0xffffffffu, rmax1, o));
        }
        float mnew0 = fmaxf(m0v, rmax0), mnew1 = fmaxf(m1v, rmax1);
        float alpha0 = __expf(m0v - mnew0), alpha1 = __expf(m1v - mnew1);

        float rsum0 = 0.0f, rsum1 = 0.0f;
#pragma unroll
        for (int nt = 0; nt < 8; nt++) {
            float p0 = __expf(sacc[nt][0] - mnew0);
            float p1 = __expf(sacc[nt][1] - mnew0);
            float p2 = __expf(sacc[nt][2] - mnew1);
            float p3 = __expf(sacc[nt][3] - mnew1);
            rsum0 += p0 + p1;
            rsum1 += p2 + p3;
            Psw32[(rq + g) * 36 + nt * 4 + t]     = packh2(p0, p1);
            Psw32[(rq + g + 8) * 36 + nt * 4 + t] = packh2(p2, p3);
        }
#pragma unroll
        for (int o = 1; o <= 2; o <<= 1) {
            rsum0 += __shfl_xor_sync(0xffffffffu, rsum0, o);
            rsum1 += __shfl_xor_sync(0xffffffffu, rsum1, o);
        }
        l0 = l0 * alpha0 + rsum0;  m0v = mnew0;
        l1 = l1 * alpha1 + rsum1;  m1v = mnew1;
#pragma unroll
        for (int nt = 0; nt < 10; nt++) {
            oacc[nt][0] *= alpha0; oacc[nt][1] *= alpha0;
            oacc[nt][2] *= alpha1; oacc[nt][3] *= alpha1;
        }
        __syncwarp();

        // ---- O += P V ----
#pragma unroll
        for (int kf = 0; kf < 4; kf++) {     // 4 x k16 = 64 tokens
            uint32_t af[4];
            int ba0 = (rq + g) * 36 + kf * 8 + t;
            int ba1 = (rq + g + 8) * 36 + kf * 8 + t;
            af[0] = Ps32[ba0];
            af[1] = Ps32[ba1];
            af[2] = Ps32[ba0 + 4];
            af[3] = Ps32[ba1 + 4];
            const int k0 = kf * 16 + 2 * t;
#pragma unroll
            for (int nt = 0; nt < 10; nt++) {
                int n = nt * 8 + g;
                uint32_t v0 = *(const uint16_t*)(Vs + k0 * PQh + n);
                uint32_t v1 = *(const uint16_t*)(Vs + (k0 + 1) * PQh + n);
                uint32_t v2 = *(const uint16_t*)(Vs + (k0 + 8) * PQh + n);
                uint32_t v3 = *(const uint16_t*)(Vs + (k0 + 9) * PQh + n);
                uint32_t bf[2];
                bf[0] = v0 | (v1 << 16);
                bf[1] = v2 | (v3 << 16);
                MMA_F16(oacc[nt], af, bf);
            }
        }
        __syncthreads();
    }

    // ---- epilogue: normalize, write fp16 ----
    const float inv0 = 1.0f / l0, inv1 = 1.0f / l1;
    const int gr0 = b * S_ + q0 + rq + g;
    __half* o0p = outp + (size_t)gr0 * HID_ + h * D_;
    __half* o1p = o0p + 8 * HID_;
#pragma unroll
    for (int nt = 0; nt < 10; nt++) {
        int c = nt * 8 + 2 * t;
        *(uint32_t*)(o0p + c) = packh2(oacc[nt][0] * inv0, oacc[nt][1] * inv0);
        *(uint32_t*)(o1p + c) = packh2(oacc[nt][2] * inv1, oacc[nt][3] * inv1);
    }
}

// ---------------------------------------------------------------------------
// kernel_launch
// ---------------------------------------------------------------------------
extern "C" void kernel_launch(void* const* d_in, const int* in_sizes, int n_in,
                              void* d_out, int out_size)
{
    const float* hidden  = (const float*)d_in[0];
    const float* cosp    = (const float*)d_in[1];
    const float* sinp    = (const float*)d_in[2];
    const float* w_qkv   = (const float*)d_in[3];
    const float* b_qkv   = (const float*)d_in[4];
    const float* w_dense = (const float*)d_in[5];
    const float* b_dense = (const float*)d_in[6];
    float* outp = (float*)d_out;

    __half *qkv, *attn, *hidH, *wqkvH, *wdH;
    cudaGetSymbolAddress((void**)&qkv,   g_qkv);
    cudaGetSymbolAddress((void**)&attn,  g_attn);
    cudaGetSymbolAddress((void**)&hidH,  g_hidH);
    cudaGetSymbolAddress((void**)&wqkvH, g_wqkvH);
    cudaGetSymbolAddress((void**)&wdH,   g_wdH);

    cudaFuncSetAttribute(mma_gemm,
                         cudaFuncAttributeMaxDynamicSharedMemorySize, GEMM_SMEM);
    cudaFuncSetAttribute(attn_kernel,
                         cudaFuncAttributeMaxDynamicSharedMemorySize, ATTN_SMEM_BYTES);

    // 0) convert inputs to fp16 (RN)
    cvt_h_kernel<<<(T_ * HID_ / 4 + 255) / 256, 256>>>(
        (const float4*)hidden, (uint2*)hidH, T_ * HID_ / 4);
    cvt_h_kernel<<<((size_t)QKV_N * HID_ / 4 + 255) / 256, 256>>>(
        (const float4*)w_qkv, (uint2*)wqkvH, QKV_N * HID_ / 4);
    cvt_h_kernel<<<((size_t)HID_ * HID_ / 4 + 255) / 256, 256>>>(
        (const float4*)w_dense, (uint2*)wdH, HID_ * HID_ / 4);

    // 1) QKV GEMM (fp16 mma) + bias -> fp16 qkv
    {
        dim3 grid(QKV_N / GN, T_ / GM);   // (60, 32)
        mma_gemm<<<grid, 256, GEMM_SMEM>>>(hidH, wqkvH, b_qkv, qkv,
                                           T_, QKV_N, HID_, 1);
    }

    // 2) partial RoPE
    {
        int total = 2 * T_ * H_ * HALF_;
        rope_kernel<<<total / 256, 256>>>(qkv, cosp, sinp);
    }

    // 3) causal flash attention (fp16 mma) -> fp16
    {
        dim3 grid(S_ / AQ, B_ * H_);      // (16, 128)
        attn_kernel<<<grid, 128, ATTN_SMEM_BYTES>>>(qkv, attn);
    }

    // 4) dense GEMM (fp16 mma) + bias -> fp32 output
    {
        dim3 grid(HID_ / GN, T_ / GM);    // (20, 32)
        mma_gemm<<<grid, 256, GEMM_SMEM>>>(attn, wdH, b_dense, outp,
                                           T_, HID_, HID_, 0);
    }
}

// round 11
// speedup vs baseline: 1.9664x; 1.0033x over previous
#include <cuda_runtime.h>
#include <cuda_fp16.h>
#include <math.h>
#include <stdint.h>

// Problem constants
#define B_   4
#define S_   1024
#define T_   4096
#define H_   32
#define D_   80
#define HID_ 2560
#define QKV_N 7680
#define HALF_ 16
#define SCALE_ 0.11180339887498948f

// ---------------------------------------------------------------------------
// Scratch (device globals)
// ---------------------------------------------------------------------------
__device__ __half g_qkv [(size_t)T_ * QKV_N];
__device__ __half g_attn[(size_t)T_ * HID_];
__device__ __half g_hidH[(size_t)T_ * HID_];
__device__ __half g_wqkvH[(size_t)QKV_N * HID_];
__device__ __half g_wdH [(size_t)HID_ * HID_];

// ---------------------------------------------------------------------------
// Helpers
// ---------------------------------------------------------------------------
#define CP_ASYNC16(dst, src) \
    asm volatile("cp.async.cg.shared.global [%0], [%1], 16;" :: "r"(dst), "l"(src) : "memory")
#define CP_COMMIT() asm volatile("cp.async.commit_group;" ::: "memory")
#define CP_WAIT0()  asm volatile("cp.async.wait_group 0;" ::: "memory")
#define CP_WAIT1()  asm volatile("cp.async.wait_group 1;" ::: "memory")

// m16n8k16 fp16 mma, fp32 accumulate.
#define MMA_F16(d, a, b) \
    asm volatile("mma.sync.aligned.m16n8k16.row.col.f32.f16.f16.f32 " \
        "{%0,%1,%2,%3}, {%4,%5,%6,%7}, {%8,%9}, {%0,%1,%2,%3};" \
        : "+f"((d)[0]), "+f"((d)[1]), "+f"((d)[2]), "+f"((d)[3]) \
        : "r"((a)[0]), "r"((a)[1]), "r"((a)[2]), "r"((a)[3]), \
          "r"((b)[0]), "r"((b)[1]))

#define LDSM_X4(r0, r1, r2, r3, addr) \
    asm volatile("ldmatrix.sync.aligned.m8n8.x4.shared.b16 {%0,%1,%2,%3}, [%4];" \
        : "=r"(r0), "=r"(r1), "=r"(r2), "=r"(r3) : "r"(addr))

__device__ __forceinline__ uint32_t smem_u32(const void* p) {
    uint32_t a;
    asm("{ .reg .u64 t; cvta.to.shared.u64 t, %1; cvt.u32.u64 %0, t; }"
        : "=r"(a) : "l"(p));
    return a;
}
__device__ __forceinline__ uint32_t packh2(float lo, float hi) {
    __half2 h = __floats2half2_rn(lo, hi);
    return *(uint32_t*)&h;
}

// ---------------------------------------------------------------------------
// fp16 mma.sync GEMM with ldmatrix fragment loads.
// C = A @ W^T + bias.  CTA 128x128, GKC=64 halves, 8 warps (64x32 each),
// 2 CTAs/SM, double-buffered cp.async, pitch 72 halves (144B rows).
// ---------------------------------------------------------------------------
#define GM 128
#define GN 128
#define GKC 64
#define PH 72
#define STGH (128 * PH)                   // halves per stage per operand
#define STGB (STGH * 2)                   // bytes per stage per operand
#define GEMM_SMEM (4 * STGB)              // 73728 bytes

__global__ __launch_bounds__(256, 2) void mma_gemm(
    const __half* __restrict__ A, const __half* __restrict__ W,
    const float* __restrict__ bias, void* __restrict__ Cv,
    int M, int N, int K, int outHalf)
{
    extern __shared__ __align__(16) uint32_t sm32[];
    const int tid  = threadIdx.x;
    const int wid  = tid >> 5;
    const int lane = tid & 31;
    const int g    = lane >> 2;
    const int t    = lane & 3;
    const int wm   = wid >> 2;
    const int wn   = wid & 3;
    const int m0 = blockIdx.y * GM;
    const int n0 = blockIdx.x * GN;
    const int nk = K / GKC;

    const uint32_t sa = smem_u32(sm32);            // A stages at [0, 2*STGB)
    const uint32_t sb = sa + 2 * STGB;             // B stages

    // cp.async mapping: per operand per stage 128 rows x 8 x16B chunks -> 4/thread.
    const int rowL = tid >> 3;
    const int cL   = tid & 7;
    const __half* srcA0 = A + (size_t)(m0 + rowL) * K + cL * 8;
    const __half* srcB0 = W + (size_t)(n0 + rowL) * K + cL * 8;
    const uint32_t d0 = (uint32_t)(rowL * 144 + cL * 16);
    const size_t rstep = (size_t)32 * K;

    // ldmatrix per-lane offsets (bytes):
    //  A mats: m=l>>3 -> (dr=(m&1)*8 rows, dk=(m>>1)*8 halves)
    const uint32_t laneOffA =
        (uint32_t)(((lane & 7) + ((lane >> 3) & 1) * 8) * 144 + (lane >> 4) * 16);
    //  B mats: m=l>>3 -> (dn=(m>>1)*8 rows, dk=(m&1)*8 halves)
    const uint32_t laneOffB =
        (uint32_t)(((lane & 7) + (lane >> 4) * 8) * 144 + ((lane >> 3) & 1) * 16);
    const uint32_t aBase = sa + (uint32_t)(wm * 64) * 144 + laneOffA;
    const uint32_t bBase = sb + (uint32_t)(wn * 32) * 144 + laneOffB;

    float acc[4][4][4];
#pragma unroll
    for (int mt = 0; mt < 4; mt++)
#pragma unroll
        for (int nt = 0; nt < 4; nt++)
#pragma unroll
            for (int r = 0; r < 4; r++) acc[mt][nt][r] = 0.0f;

    // Prologue: stage 0, chunk 0
#pragma unroll
    for (int u = 0; u < 4; u++) {
        CP_ASYNC16(sa + d0 + u * 4608, srcA0 + u * rstep);
        CP_ASYNC16(sb + d0 + u * 4608, srcB0 + u * rstep);
    }
    CP_COMMIT();

    for (int i = 0; i < nk; i++) {
        const int s = i & 1;
        if (i + 1 < nk) {
            const int s2 = (i + 1) & 1;
            const int kt = (i + 1) * GKC;
            const uint32_t ab = sa + s2 * STGB;
            const uint32_t bb = sb + s2 * STGB;
#pragma unroll
            for (int u = 0; u < 4; u++) {
                CP_ASYNC16(ab + d0 + u * 4608, srcA0 + kt + u * rstep);
                CP_ASYNC16(bb + d0 + u * 4608, srcB0 + kt + u * rstep);
            }
            CP_COMMIT();
            CP_WAIT1();
        } else {
            CP_WAIT0();
        }
        __syncthreads();

        const uint32_t aStg = aBase + s * STGB;
        const uint32_t bStg = bBase + s * STGB;
#pragma unroll
        for (int ks = 0; ks < 4; ks++) {           // 4 x k16 steps
            const uint32_t kOff = ks * 32;         // 16 halves = 32 bytes
            uint32_t af[4][4], bf[4][2];
#pragma unroll
            for (int mt = 0; mt < 4; mt++)
                LDSM_X4(af[mt][0], af[mt][1], af[mt][2], af[mt][3],
                        aStg + (uint32_t)(mt * 16) * 144 + kOff);
#pragma unroll
            for (int j = 0; j < 2; j++)
                LDSM_X4(bf[2*j][0], bf[2*j][1], bf[2*j+1][0], bf[2*j+1][1],
                        bStg + (uint32_t)(j * 16) * 144 + kOff);
#pragma unroll
            for (int mt = 0; mt < 4; mt++)
#pragma unroll
                for (int nt = 0; nt < 4; nt++)
                    MMA_F16(acc[mt][nt], af[mt], bf[nt]);
        }
        __syncthreads();
    }

    // Epilogue: bias + store.
#pragma unroll
    for (int mt = 0; mt < 4; mt++) {
        int r = m0 + wm * 64 + mt * 16 + g;
#pragma unroll
        for (int nt = 0; nt < 4; nt++) {
            int c = n0 + wn * 32 + nt * 8 + t * 2;
            float b0 = bias[c], b1 = bias[c + 1];
            float o0 = acc[mt][nt][0] + b0, o1 = acc[mt][nt][1] + b1;
            float o2 = acc[mt][nt][2] + b0, o3 = acc[mt][nt][3] + b1;
            if (outHalf) {
                __half* C = (__half*)Cv;
                *(uint32_t*)(C + (size_t)r * N + c)       = packh2(o0, o1);
                *(uint32_t*)(C + (size_t)(r + 8) * N + c) = packh2(o2, o3);
            } else {
                float* C = (float*)Cv;
                *(float2*)(C + (size_t)r * N + c)       = make_float2(o0, o1);
                *(float2*)(C + (size_t)(r + 8) * N + c) = make_float2(o2, o3);
            }
        }
    }
}

// ---------------------------------------------------------------------------
// fp32 -> fp16 convert (RN)
// ---------------------------------------------------------------------------
__global__ __launch_bounds__(256) void cvt_h_kernel(
    const float4* __restrict__ in, uint2* __restrict__ out, int n4)
{
    int i = blockIdx.x * 256 + threadIdx.x;
    if (i >= n4) return;
    float4 v = in[i];
    uint2 o;
    o.x = packh2(v.x, v.y);
    o.y = packh2(v.z, v.w);
    out[i] = o;
}

// ---------------------------------------------------------------------------
// Partial rotary on fp16 qkv (in place), fp32 math.
// ---------------------------------------------------------------------------
__global__ __launch_bounds__(256) void rope_kernel(
    __half* __restrict__ qkv, const float* __restrict__ cosp,
    const float* __restrict__ sinp)
{
    int idx = blockIdx.x * blockDim.x + threadIdx.x;
    int i = idx & (HALF_ - 1);
    int h = (idx >> 4) & (H_ - 1);
    int t = (idx >> 9) & (T_ - 1);
    int which = idx >> 21;
    __half* base = qkv + (size_t)t * QKV_N + which * HID_ + h * D_;
    float c = cosp[t * HALF_ + i];
    float s = sinp[t * HALF_ + i];
    float x1 = __half2float(base[i]);
    float x2 = __half2float(base[i + HALF_]);
    base[i]         = __float2half_rn(x1 * c - x2 * s);
    base[i + HALF_] = __float2half_rn(x2 * c + x1 * s);
}

// ---------------------------------------------------------------------------
// Causal flash attention, fp16 mma.sync m16n8k16 (Round-10 proven).
// ---------------------------------------------------------------------------
#define AQ 64
#define AKV 64
#define PQh 88
#define PPh 72
#define ATTN_SMEM_BYTES ((3 * AQ * PQh + AQ * PPh) * 2)   // 43008

__global__ __launch_bounds__(128) void attn_kernel(
    const __half* __restrict__ qkv, __half* __restrict__ outp)
{
    extern __shared__ __align__(16) __half smh[];
    __half* Qs = smh;
    __half* Ks = Qs + AQ * PQh;
    __half* Vs = Ks + AKV * PQh;
    __half* Ps = Vs + AKV * PQh;
    const uint32_t* Qs32 = (const uint32_t*)Qs;
    const uint32_t* Ks32 = (const uint32_t*)Ks;
    const uint32_t* Ps32 = (const uint32_t*)Ps;
    uint32_t* Psw32 = (uint32_t*)Ps;

    const int bh = blockIdx.y;
    const int b  = bh >> 5;
    const int h  = bh & 31;
    const int qt = blockIdx.x;
    const int q0 = qt * AQ;
    const int tid = threadIdx.x;
    const int lane = tid & 31;
    const int w = tid >> 5;
    const int g = lane >> 2;
    const int t = lane & 3;
    const int rq = w * 16;

    const __half* Qg = qkv + (size_t)(b * S_) * QKV_N + h * D_;
    const __half* Kg = Qg + HID_;
    const __half* Vg = Qg + 2 * HID_;

    {
        uint4* Q4 = (uint4*)Qs;
        for (int u = tid; u < AQ * 10; u += 128) {
            int r = u / 10, c8 = u % 10;
            Q4[r * 11 + c8] = *(const uint4*)(Qg + (size_t)(q0 + r) * QKV_N + c8 * 8);
        }
    }

    float m0v = -1e30f, m1v = -1e30f, l0 = 0.0f, l1 = 0.0f;
    float oacc[10][4];
#pragma unroll
    for (int nt = 0; nt < 10; nt++)
#pragma unroll
        for (int r = 0; r < 4; r++) oacc[nt][r] = 0.0f;

    for (int jt = 0; jt <= qt; jt++) {
        {
            uint4* K4 = (uint4*)Ks;
            uint4* V4 = (uint4*)Vs;
            for (int u = tid; u < AKV * 10; u += 128) {
                int r = u / 10, c8 = u % 10;
                K4[r * 11 + c8] = *(const uint4*)(Kg + (size_t)(jt * AKV + r) * QKV_N + c8 * 8);
                V4[r * 11 + c8] = *(const uint4*)(Vg + (size_t)(jt * AKV + r) * QKV_N + c8 * 8);
            }
        }
        __syncthreads();

        float sacc[8][4];
#pragma unroll
        for (int nt = 0; nt < 8; nt++)
#pragma unroll
            for (int r = 0; r < 4; r++) sacc[nt][r] = 0.0f;

#pragma unroll
        for (int kf = 0; kf < 5; kf++) {
            uint32_t af[4];
            int ba0 = (rq + g) * 44 + kf * 8 + t;
            int ba1 = (rq + g + 8) * 44 + kf * 8 + t;
            af[0] = Qs32[ba0];
            af[1] = Qs32[ba1];
            af[2] = Qs32[ba0 + 4];
            af[3] = Qs32[ba1 + 4];
#pragma unroll
            for (int nt = 0; nt < 8; nt++) {
                uint32_t bf[2];
                int bb = (nt * 8 + g) * 44 + kf * 8 + t;
                bf[0] = Ks32[bb];
                bf[1] = Ks32[bb + 4];
                MMA_F16(sacc[nt], af, bf);
            }
        }

        const int r0 = q0 + rq + g;
        const int r1 = r0 + 8;
#pragma unroll
        for (int nt = 0; nt < 8; nt++) {
            int c0 = jt * AKV + nt * 8 + 2 * t;
            int c1 = c0 + 1;
            sacc[nt][0] = (c0 > r0) ? -1e30f : sacc[nt][0] * SCALE_;
            sacc[nt][1] = (c1 > r0) ? -1e30f : sacc[nt][1] * SCALE_;
            sacc[nt][2] = (c0 > r1) ? -1e30f : sacc[nt][2] * SCALE_;
            sacc[nt][3] = (c1 > r1) ? -1e30f : sacc[nt][3] * SCALE_;
        }

        float rmax0 = -1e30f, rmax1 = -1e30f;
#pragma unroll
        for (int nt = 0; nt < 8; nt++) {
            rmax0 = fmaxf(rmax0, fmaxf(sacc[nt][0], sacc[nt][1]));
            rmax1 = fmaxf(rmax1, fmaxf(sacc[nt][2], sacc[nt][3]));
        }
#pragma unroll
        for (int o = 1; o <= 2; o <<= 1) {
            rmax0 = fmaxf(rmax0, __shfl_xor_sync(0xffffffffu, rmax0, o));
            rmax1 = fmaxf(rmax1, __shfl_xor_sync(0xffffffffu, rmax1, o));
        }
        float mnew0 = fmaxf(m0v, rmax0), mnew1 = fmaxf(m1v, rmax1);
        float alpha0 = __expf(m0v - mnew0), alpha1 = __expf(m1v - mnew1);

        float rsum0 = 0.0f, rsum1 = 0.0f;
#pragma unroll
        for (int nt = 0; nt < 8; nt++) {
            float p0 = __expf(sacc[nt][0] - mnew0);
            float p1 = __expf(sacc[nt][1] - mnew0);
            float p2 = __expf(sacc[nt][2] - mnew1);
            float p3 = __expf(sacc[nt][3] - mnew1);
            rsum0 += p0 + p1;
            rsum1 += p2 + p3;
            Psw32[(rq + g) * 36 + nt * 4 + t]     = packh2(p0, p1);
            Psw32[(rq + g + 8) * 36 + nt * 4 + t] = packh2(p2, p3);
        }
#pragma unroll
        for (int o = 1; o <= 2; o <<= 1) {
            rsum0 += __shfl_xor_sync(0xffffffffu, rsum0, o);
            rsum1 += __shfl_xor_sync(0xffffffffu, rsum1, o);
        }
        l0 = l0 * alpha0 + rsum0;  m0v = mnew0;
        l1 = l1 * alpha1 + rsum1;  m1v = mnew1;
#pragma unroll
        for (int nt = 0; nt < 10; nt++) {
            oacc[nt][0] *= alpha0; oacc[nt][1] *= alpha0;
            oacc[nt][2] *= alpha1; oacc[nt][3] *= alpha1;
        }
        __syncwarp();

#pragma unroll
        for (int kf = 0; kf < 4; kf++) {
            uint32_t af[4];
            int ba0 = (rq + g) * 36 + kf * 8 + t;
            int ba1 = (rq + g + 8) * 36 + kf * 8 + t;
            af[0] = Ps32[ba0];
            af[1] = Ps32[ba1];
            af[2] = Ps32[ba0 + 4];
            af[3] = Ps32[ba1 + 4];
            const int k0 = kf * 16 + 2 * t;
#pragma unroll
            for (int nt = 0; nt < 10; nt++) {
                int n = nt * 8 + g;
                uint32_t v0 = *(const uint16_t*)(Vs + k0 * PQh + n);
                uint32_t v1 = *(const uint16_t*)(Vs + (k0 + 1) * PQh + n);
                uint32_t v2 = *(const uint16_t*)(Vs + (k0 + 8) * PQh + n);
                uint32_t v3 = *(const uint16_t*)(Vs + (k0 + 9) * PQh + n);
                uint32_t bf[2];
                bf[0] = v0 | (v1 << 16);
                bf[1] = v2 | (v3 << 16);
                MMA_F16(oacc[nt], af, bf);
            }
        }
        __syncthreads();
    }

    const float inv0 = 1.0f / l0, inv1 = 1.0f / l1;
    const int gr0 = b * S_ + q0 + rq + g;
    __half* o0p = outp + (size_t)gr0 * HID_ + h * D_;
    __half* o1p = o0p + 8 * HID_;
#pragma unroll
    for (int nt = 0; nt < 10; nt++) {
        int c = nt * 8 + 2 * t;
        *(uint32_t*)(o0p + c) = packh2(oacc[nt][0] * inv0, oacc[nt][1] * inv0);
        *(uint32_t*)(o1p + c) = packh2(oacc[nt][2] * inv1, oacc[nt][3] * inv1);
    }
}

// ---------------------------------------------------------------------------
// kernel_launch
// ---------------------------------------------------------------------------
extern "C" void kernel_launch(void* const* d_in, const int* in_sizes, int n_in,
                              void* d_out, int out_size)
{
    const float* hidden  = (const float*)d_in[0];
    const float* cosp    = (const float*)d_in[1];
    const float* sinp    = (const float*)d_in[2];
    const float* w_qkv   = (const float*)d_in[3];
    const float* b_qkv   = (const float*)d_in[4];
    const float* w_dense = (const float*)d_in[5];
    const float* b_dense = (const float*)d_in[6];
    float* outp = (float*)d_out;

    __half *qkv, *attn, *hidH, *wqkvH, *wdH;
    cudaGetSymbolAddress((void**)&qkv,   g_qkv);
    cudaGetSymbolAddress((void**)&attn,  g_attn);
    cudaGetSymbolAddress((void**)&hidH,  g_hidH);
    cudaGetSymbolAddress((void**)&wqkvH, g_wqkvH);
    cudaGetSymbolAddress((void**)&wdH,   g_wdH);

    cudaFuncSetAttribute(mma_gemm,
                         cudaFuncAttributeMaxDynamicSharedMemorySize, GEMM_SMEM);
    cudaFuncSetAttribute(attn_kernel,
                         cudaFuncAttributeMaxDynamicSharedMemorySize, ATTN_SMEM_BYTES);

    // 0) convert inputs to fp16 (RN)
    cvt_h_kernel<<<(T_ * HID_ / 4 + 255) / 256, 256>>>(
        (const float4*)hidden, (uint2*)hidH, T_ * HID_ / 4);
    cvt_h_kernel<<<((size_t)QKV_N * HID_ / 4 + 255) / 256, 256>>>(
        (const float4*)w_qkv, (uint2*)wqkvH, QKV_N * HID_ / 4);
    cvt_h_kernel<<<((size_t)HID_ * HID_ / 4 + 255) / 256, 256>>>(
        (const float4*)w_dense, (uint2*)wdH, HID_ * HID_ / 4);

    // 1) QKV GEMM (fp16 mma + ldmatrix) + bias -> fp16 qkv
    {
        dim3 grid(QKV_N / GN, T_ / GM);   // (60, 32)
        mma_gemm<<<grid, 256, GEMM_SMEM>>>(hidH, wqkvH, b_qkv, qkv,
                                           T_, QKV_N, HID_, 1);
    }

    // 2) partial RoPE
    {
        int total = 2 * T_ * H_ * HALF_;
        rope_kernel<<<total / 256, 256>>>(qkv, cosp, sinp);
    }

    // 3) causal flash attention (fp16 mma) -> fp16
    {
        dim3 grid(S_ / AQ, B_ * H_);      // (16, 128)
        attn_kernel<<<grid, 128, ATTN_SMEM_BYTES>>>(qkv, attn);
    }

    // 4) dense GEMM (fp16 mma + ldmatrix) + bias -> fp32 output
    {
        dim3 grid(HID_ / GN, T_ / GM);    // (20, 32)
        mma_gemm<<<grid, 256, GEMM_SMEM>>>(attn, wdH, b_dense, outp,
                                           T_, HID_, HID_, 0);
    }
}